// round 3
// baseline (speedup 1.0000x reference)
#include <cuda_runtime.h>
#include <cuda_bf16.h>
#include <math.h>

#define Bn 8
#define An 100000
#define Cn 80
#define TOPN 1000
#define MAXOBJ 100
#define CAP 4096
#define MASKW 16   // 1024 bits >= TOPN

#define BIN_BASE (0x3D4CCCCDu >> 10)                       // bits(0.05f) >> 10
#define NBINS ((int)((0x3F7FFFFFu >> 10) - BIN_BASE) + 1)  // ~36045

// per-warp tile: 32 anchors x 20 float4, padded row stride 21 (bank-conflict-free)
#define ROWP 21
#define WARPS 8
#define TILE_F4 (32 * ROWP)                 // 672 float4 per warp
#define SCORE_SMEM (WARPS * TILE_F4 * 16)   // 86016 bytes

// ------------------- scratch (device globals; no allocation) -------------------
__device__ float              g_scores[Bn * An];
__device__ unsigned           g_hist[Bn * NBINS];
__device__ unsigned           g_thr[Bn];
__device__ int                g_candCount[Bn];
__device__ unsigned long long g_cand[Bn * CAP];
__device__ unsigned long long g_top[Bn * TOPN];
__device__ float              g_tscore[Bn * TOPN];
__device__ int                g_tcls[Bn * TOPN];
__device__ int                g_tvalid[Bn * TOPN];
__device__ float4             g_tbox[Bn * TOPN];
__device__ unsigned long long g_mask[Bn * TOPN * MASKW];

// ------------------- kernels -------------------

__global__ void k_zero() {
    int i = blockIdx.x * blockDim.x + threadIdx.x;
    if (i < Bn * NBINS) g_hist[i] = 0u;
    if (i < Bn) g_candCount[i] = 0;
}

// Max-of-80 per anchor with fully coalesced loads via per-warp smem tile.
// No argmax / decode here (done post-selection).
__global__ void k_score(const float4* __restrict__ cls4) {
    extern __shared__ float4 tile[];
    int warp = threadIdx.x >> 5, lane = threadIdx.x & 31;
    int anchor0 = blockIdx.x * (WARPS * 32) + warp * 32;   // 256 anchors/block, exact
    float4* tw = tile + warp * TILE_F4;
    const float4* src = cls4 + (size_t)anchor0 * (Cn / 4);

#pragma unroll
    for (int k = 0; k < 20; k++) {
        int li = lane + 32 * k;            // linear float4 index in the 32x20 tile
        float4 v = src[li];                // coalesced: 32 consecutive float4s
        int a = li / 20, j = li - a * 20;
        tw[a * ROWP + j] = v;
    }
    __syncwarp();

    const float4* myrow = tw + lane * ROWP;
    float4 m = myrow[0];
    float best = fmaxf(fmaxf(m.x, m.y), fmaxf(m.z, m.w));
#pragma unroll
    for (int j = 1; j < 20; j++) {
        float4 v = myrow[j];
        best = fmaxf(best, fmaxf(fmaxf(v.x, v.y), fmaxf(v.z, v.w)));
    }

    int idx = anchor0 + lane;
    g_scores[idx] = best;
    if (best > 0.05f) {
        unsigned bits = __float_as_uint(best);
        int bin = (int)((bits >> 10) - BIN_BASE);
        bin = max(0, min(NBINS - 1, bin));
        atomicAdd(&g_hist[(idx / An) * NBINS + bin], 1u);
    }
}

// Per-image: scan histogram from the top to find the bin where cum >= TOPN
__global__ void k_thresh() {
    int b = blockIdx.x;
    __shared__ unsigned vals[256];
    __shared__ int s_cum, s_done;
    __shared__ unsigned s_thr;
    if (threadIdx.x == 0) { s_cum = 0; s_done = 0; s_thr = 0u; }
    __syncthreads();
    int nch = (NBINS + 255) / 256;
    for (int ci = nch - 1; ci >= 0; --ci) {
        int bin = ci * 256 + threadIdx.x;
        vals[threadIdx.x] = (bin < NBINS) ? g_hist[b * NBINS + bin] : 0u;
        __syncthreads();
        if (threadIdx.x == 0) {
            int sum = 0;
            for (int k = 0; k < 256; k++) sum += (int)vals[k];
            if (s_cum + sum >= TOPN) {
                int cum = s_cum;
                for (int k = 255; k >= 0; --k) {
                    cum += (int)vals[k];
                    if (cum >= TOPN) {
                        s_thr = (BIN_BASE + (unsigned)(ci * 256 + k)) << 10;
                        break;
                    }
                }
                s_done = 1;
            } else {
                s_cum += sum;
            }
        }
        __syncthreads();
        if (s_done) break;
    }
    if (threadIdx.x == 0) g_thr[b] = s_thr;
}

__global__ void k_collect() {
    int idx = blockIdx.x * blockDim.x + threadIdx.x;
    if (idx >= Bn * An) return;
    float s = g_scores[idx];
    if (s > 0.05f) {
        int b = idx / An;
        unsigned bits = __float_as_uint(s);
        if (bits >= g_thr[b]) {
            int pos = atomicAdd(&g_candCount[b], 1);
            if (pos < CAP) {
                unsigned a = (unsigned)(idx - b * An);
                g_cand[b * CAP + pos] =
                    ((unsigned long long)bits << 32) | (unsigned long long)(~a);
            }
        }
    }
}

// Per-image bitonic sort (descending) of candidate keys; emit sorted top-1000 keys
__global__ void k_sort() {
    int b = blockIdx.x, t = threadIdx.x;
    __shared__ unsigned long long key[CAP];
    int cnt = min(g_candCount[b], CAP);
    for (int i = t; i < CAP; i += blockDim.x)
        key[i] = (i < cnt) ? g_cand[b * CAP + i] : 0ull;
    __syncthreads();
    for (int k = 2; k <= CAP; k <<= 1) {
        for (int j = k >> 1; j > 0; j >>= 1) {
            for (int i = t; i < CAP; i += blockDim.x) {
                int ixj = i ^ j;
                if (ixj > i) {
                    unsigned long long x = key[i], y = key[ixj];
                    bool desc = ((i & k) == 0);
                    if ((x < y) == desc) { key[i] = y; key[ixj] = x; }
                }
            }
            __syncthreads();
        }
    }
    for (int i = t; i < TOPN; i += blockDim.x)
        g_top[b * TOPN + i] = key[i];
}

// Warp per selected candidate: argmax over 80 (coalesced re-read) + box decode
__global__ void k_gather(const float* __restrict__ cls,
                         const float4* __restrict__ reg,
                         const float4* __restrict__ anc) {
    int b = blockIdx.y;
    int i = blockIdx.x * (blockDim.x >> 5) + (threadIdx.x >> 5);
    int lane = threadIdx.x & 31;
    if (i >= TOPN) return;
    int o = b * TOPN + i;
    unsigned long long kk = g_top[o];
    if (!kk) {
        if (lane == 0) {
            g_tscore[o] = -1.f; g_tcls[o] = -1; g_tvalid[o] = 0;
            g_tbox[o] = make_float4(0.f, 0.f, 0.f, 0.f);
        }
        return;
    }
    unsigned abits = ~(unsigned)kk;
    int arow = b * An + (int)abits;
    const float* rowp = cls + (size_t)arow * Cn;
    float bv = -1e30f; int bi = Cn;
    for (int c = lane; c < Cn; c += 32) {
        float v = rowp[c];
        if (v > bv) { bv = v; bi = c; }
    }
#pragma unroll
    for (int off = 16; off; off >>= 1) {
        float ov = __shfl_down_sync(0xffffffffu, bv, off);
        int   oi = __shfl_down_sync(0xffffffffu, bi, off);
        if (ov > bv || (ov == bv && oi < bi)) { bv = ov; bi = oi; }
    }
    if (lane == 0) {
        float4 r = reg[arow];
        float4 a = anc[arow];
        float aw = __fsub_rn(a.z, a.x);
        float ah = __fsub_rn(a.w, a.y);
        float acx = __fadd_rn(a.x, __fmul_rn(0.5f, aw));
        float acy = __fadd_rn(a.y, __fmul_rn(0.5f, ah));
        float pw = __fmul_rn((float)exp((double)r.z), aw);
        float ph = __fmul_rn((float)exp((double)r.w), ah);
        float pcx = __fadd_rn(__fmul_rn(r.x, aw), acx);
        float pcy = __fadd_rn(__fmul_rn(r.y, ah), acy);
        float4 bx;
        bx.x = truncf(__fsub_rn(pcx, __fmul_rn(0.5f, pw)));
        bx.y = truncf(__fsub_rn(pcy, __fmul_rn(0.5f, ph)));
        bx.z = truncf(__fadd_rn(pcx, __fmul_rn(0.5f, pw)));
        bx.w = truncf(__fadd_rn(pcy, __fmul_rn(0.5f, ph)));
        g_tscore[o] = __uint_as_float((unsigned)(kk >> 32));
        g_tcls[o] = bi;
        g_tvalid[o] = 1;
        g_tbox[o] = bx;
    }
}

// 1000x1000 IoU suppression mask (bit set: j suppressed by i, j > i, iou >= 0.5)
__global__ void k_mask() {
    int b = blockIdx.z, rb = blockIdx.y, cb = blockIdx.x, t = threadIdx.x;
    __shared__ float4 cbox[64];
    __shared__ float carea[64];
    int j0 = cb * 64;
    int j = j0 + t;
    float4 bj = (j < TOPN) ? g_tbox[b * TOPN + j] : make_float4(0.f, 0.f, 0.f, 0.f);
    cbox[t] = bj;
    carea[t] = fmaxf((bj.z - bj.x) * (bj.w - bj.y), 1e-4f);
    __syncthreads();
    int i = rb * 64 + t;
    if (i < TOPN) {
        float4 bi = g_tbox[b * TOPN + i];
        float ai = fmaxf((bi.z - bi.x) * (bi.w - bi.y), 1e-4f);
        unsigned long long bits = 0ull;
        for (int jj = 0; jj < 64; jj++) {
            int jg = j0 + jj;
            if (jg > i && jg < TOPN) {
                float4 bb = cbox[jj];
                float tlx = fmaxf(bi.x, bb.x), tly = fmaxf(bi.y, bb.y);
                float brx = fminf(bi.z, bb.z), bry = fminf(bi.w, bb.w);
                float iw = fmaxf(brx - tlx, 0.f), ih = fmaxf(bry - tly, 0.f);
                float inter = iw * ih;
                float un = fmaxf(ai + carea[jj] - inter, 1e-4f);
                if (inter / un >= 0.5f) bits |= (1ull << jj);
            }
        }
        g_mask[(b * TOPN + i) * MASKW + cb] = bits;
    }
}

// Serial greedy scan over mask (staged in shared), compact first MAXOBJ
__global__ void k_final(float* __restrict__ out) {
    int b = blockIdx.x, t = threadIdx.x;
    extern __shared__ unsigned long long sm[];
    unsigned long long* smask = sm;
    unsigned long long* srem = sm + TOPN * MASKW;

    for (int i = t; i < TOPN * MASKW; i += blockDim.x)
        smask[i] = g_mask[b * TOPN * MASKW + i];
    if (t < MASKW) {
        unsigned long long w = 0ull;
        for (int k = 0; k < 64; k++) {
            int i = t * 64 + k;
            if (i >= TOPN || !g_tvalid[b * TOPN + i]) w |= (1ull << k);
        }
        srem[t] = w;
    }
    float* out_s = out;
    float* out_c = out + Bn * MAXOBJ;
    float* out_b = out + 2 * Bn * MAXOBJ;
    for (int k = t; k < MAXOBJ; k += blockDim.x) {
        out_s[b * MAXOBJ + k] = -1.f;
        out_c[b * MAXOBJ + k] = -1.f;
        ((float4*)out_b)[b * MAXOBJ + k] = make_float4(0.f, 0.f, 0.f, 0.f);
    }
    __syncthreads();

    if (t == 0) {
        unsigned long long rem[MASKW];
#pragma unroll
        for (int w = 0; w < MASKW; w++) rem[w] = srem[w];
        int nk = 0;
        for (int i = 0; i < TOPN && nk < MAXOBJ; i++) {
            if ((rem[i >> 6] >> (i & 63)) & 1ull) continue;
            int o = b * TOPN + i;
            out_s[b * MAXOBJ + nk] = g_tscore[o];
            out_c[b * MAXOBJ + nk] = (float)g_tcls[o];
            ((float4*)out_b)[b * MAXOBJ + nk] = g_tbox[o];
            nk++;
#pragma unroll
            for (int w = 0; w < MASKW; w++) rem[w] |= smask[i * MASKW + w];
        }
    }
}

// ------------------- launch -------------------
extern "C" void kernel_launch(void* const* d_in, const int* in_sizes, int n_in,
                              void* d_out, int out_size) {
    const float*  cls = (const float*)d_in[0];
    const float4* reg = (const float4*)d_in[1];
    const float4* anc = (const float4*)d_in[2];
    float* out = (float*)d_out;

    const int FINAL_SMEM = (TOPN * MASKW + MASKW) * (int)sizeof(unsigned long long);
    cudaFuncSetAttribute(k_final, cudaFuncAttributeMaxDynamicSharedMemorySize, FINAL_SMEM);
    cudaFuncSetAttribute(k_score, cudaFuncAttributeMaxDynamicSharedMemorySize, SCORE_SMEM);

    int nzero = Bn * NBINS;
    k_zero<<<(nzero + 255) / 256, 256>>>();
    int total = Bn * An;
    k_score<<<total / (WARPS * 32), WARPS * 32, SCORE_SMEM>>>((const float4*)cls);
    k_thresh<<<Bn, 256>>>();
    k_collect<<<(total + 255) / 256, 256>>>();
    k_sort<<<Bn, 1024>>>();
    k_gather<<<dim3((TOPN + 3) / 4, Bn), 128>>>(cls, reg, anc);
    k_mask<<<dim3((TOPN + 63) / 64, (TOPN + 63) / 64, Bn), 64>>>();
    k_final<<<Bn, 256, FINAL_SMEM>>>(out);
}

// round 5
// speedup vs baseline: 1.0212x; 1.0212x over previous
#include <cuda_runtime.h>
#include <cuda_bf16.h>
#include <math.h>

#define Bn 8
#define An 100000
#define Cn 80
#define TOPN 1000
#define MAXOBJ 100
#define CAP 2048
#define MASKW 16   // 1024 bits >= TOPN

#define BIN_BASE (0x3D4CCCCDu >> 10)                       // bits(0.05f) >> 10
#define NBINS ((int)((0x3F7FFFFFu >> 10) - BIN_BASE) + 1)  // ~36045

// ------------------- scratch (device globals; no allocation) -------------------
__device__ float              g_scores[Bn * An];
__device__ unsigned           g_hist[Bn * NBINS];
__device__ unsigned           g_thr[Bn];
__device__ int                g_candCount[Bn];
__device__ unsigned long long g_cand[Bn * CAP];
__device__ unsigned long long g_top[Bn * TOPN];
__device__ float              g_tscore[Bn * TOPN];
__device__ int                g_tcls[Bn * TOPN];
__device__ int                g_tvalid[Bn * TOPN];
__device__ float4             g_tbox[Bn * TOPN];
__device__ unsigned long long g_mask[Bn * TOPN * MASKW];

// ------------------- kernels -------------------

__global__ void k_dummy() {}

__global__ void k_zero() {
    int i = blockIdx.x * blockDim.x + threadIdx.x;
    if (i < Bn * NBINS) g_hist[i] = 0u;
    if (i < Bn) g_candCount[i] = 0;
}

// 4 threads per anchor: coalesced 64B-per-group LDG.128, shfl-xor max reduction.
// No smem, low regs -> full occupancy, DRAM-bound by design.
__global__ void k_score(const float4* __restrict__ cls4) {
    int g = blockIdx.x * blockDim.x + threadIdx.x;
    int a = g >> 2;          // anchor
    int q = g & 3;           // quarter of the row
    if (a >= Bn * An) return;
    const float4* row = cls4 + (size_t)a * (Cn / 4);
    float best = -1e30f;
#pragma unroll
    for (int k = 0; k < 5; k++) {
        float4 v = row[q + 4 * k];
        best = fmaxf(best, fmaxf(fmaxf(v.x, v.y), fmaxf(v.z, v.w)));
    }
    best = fmaxf(best, __shfl_xor_sync(0xffffffffu, best, 1));
    best = fmaxf(best, __shfl_xor_sync(0xffffffffu, best, 2));
    if (q == 0) {
        g_scores[a] = best;
        if (best > 0.05f) {
            unsigned bits = __float_as_uint(best);
            int bin = (int)((bits >> 10) - BIN_BASE);
            bin = max(0, min(NBINS - 1, bin));
            atomicAdd(&g_hist[(a / An) * NBINS + bin], 1u);
        }
    }
}

// Per-image: scan histogram from the top to find the bin where cum >= TOPN
__global__ void k_thresh() {
    int b = blockIdx.x;
    __shared__ unsigned vals[256];
    __shared__ int s_cum, s_done;
    __shared__ unsigned s_thr;
    if (threadIdx.x == 0) { s_cum = 0; s_done = 0; s_thr = 0u; }
    __syncthreads();
    int nch = (NBINS + 255) / 256;
    for (int ci = nch - 1; ci >= 0; --ci) {
        int bin = ci * 256 + threadIdx.x;
        vals[threadIdx.x] = (bin < NBINS) ? g_hist[b * NBINS + bin] : 0u;
        __syncthreads();
        if (threadIdx.x == 0) {
            int sum = 0;
            for (int k = 0; k < 256; k++) sum += (int)vals[k];
            if (s_cum + sum >= TOPN) {
                int cum = s_cum;
                for (int k = 255; k >= 0; --k) {
                    cum += (int)vals[k];
                    if (cum >= TOPN) {
                        s_thr = (BIN_BASE + (unsigned)(ci * 256 + k)) << 10;
                        break;
                    }
                }
                s_done = 1;
            } else {
                s_cum += sum;
            }
        }
        __syncthreads();
        if (s_done) break;
    }
    if (threadIdx.x == 0) g_thr[b] = s_thr;
}

// float4-vectorized candidate collection (An % 4 == 0, so a float4 never
// straddles an image boundary)
__global__ void k_collect() {
    int i4 = blockIdx.x * blockDim.x + threadIdx.x;
    if (i4 >= (Bn * An) / 4) return;
    float4 s4 = ((const float4*)g_scores)[i4];
    int base = i4 * 4;
    int b = base / An;
    unsigned thr = g_thr[b];
    float sv[4] = {s4.x, s4.y, s4.z, s4.w};
#pragma unroll
    for (int k = 0; k < 4; k++) {
        float s = sv[k];
        if (s > 0.05f) {
            unsigned bits = __float_as_uint(s);
            if (bits >= thr) {
                int pos = atomicAdd(&g_candCount[b], 1);
                if (pos < CAP) {
                    unsigned a = (unsigned)(base + k - b * An);
                    g_cand[b * CAP + pos] =
                        ((unsigned long long)bits << 32) | (unsigned long long)(~a);
                }
            }
        }
    }
}

// Per-image bitonic sort (descending) of candidate keys; emit sorted top-1000 keys
__global__ void k_sort() {
    int b = blockIdx.x, t = threadIdx.x;
    __shared__ unsigned long long key[CAP];
    int cnt = min(g_candCount[b], CAP);
    for (int i = t; i < CAP; i += blockDim.x)
        key[i] = (i < cnt) ? g_cand[b * CAP + i] : 0ull;
    __syncthreads();
    for (int k = 2; k <= CAP; k <<= 1) {
        for (int j = k >> 1; j > 0; j >>= 1) {
            for (int i = t; i < CAP; i += blockDim.x) {
                int ixj = i ^ j;
                if (ixj > i) {
                    unsigned long long x = key[i], y = key[ixj];
                    bool desc = ((i & k) == 0);
                    if ((x < y) == desc) { key[i] = y; key[ixj] = x; }
                }
            }
            __syncthreads();
        }
    }
    for (int i = t; i < TOPN; i += blockDim.x)
        g_top[b * TOPN + i] = key[i];
}

// Warp per selected candidate: argmax over 80 (coalesced re-read) + box decode
__global__ void k_gather(const float* __restrict__ cls,
                         const float4* __restrict__ reg,
                         const float4* __restrict__ anc) {
    int b = blockIdx.y;
    int i = blockIdx.x * (blockDim.x >> 5) + (threadIdx.x >> 5);
    int lane = threadIdx.x & 31;
    if (i >= TOPN) return;
    int o = b * TOPN + i;
    unsigned long long kk = g_top[o];
    if (!kk) {
        if (lane == 0) {
            g_tscore[o] = -1.f; g_tcls[o] = -1; g_tvalid[o] = 0;
            g_tbox[o] = make_float4(0.f, 0.f, 0.f, 0.f);
        }
        return;
    }
    unsigned abits = ~(unsigned)kk;
    int arow = b * An + (int)abits;
    const float* rowp = cls + (size_t)arow * Cn;
    float bv = -1e30f; int bi = Cn;
    for (int c = lane; c < Cn; c += 32) {
        float v = rowp[c];
        if (v > bv) { bv = v; bi = c; }
    }
#pragma unroll
    for (int off = 16; off; off >>= 1) {
        float ov = __shfl_down_sync(0xffffffffu, bv, off);
        int   oi = __shfl_down_sync(0xffffffffu, bi, off);
        if (ov > bv || (ov == bv && oi < bi)) { bv = ov; bi = oi; }
    }
    if (lane == 0) {
        float4 r = reg[arow];
        float4 a = anc[arow];
        float aw = __fsub_rn(a.z, a.x);
        float ah = __fsub_rn(a.w, a.y);
        float acx = __fadd_rn(a.x, __fmul_rn(0.5f, aw));
        float acy = __fadd_rn(a.y, __fmul_rn(0.5f, ah));
        float pw = __fmul_rn((float)exp((double)r.z), aw);
        float ph = __fmul_rn((float)exp((double)r.w), ah);
        float pcx = __fadd_rn(__fmul_rn(r.x, aw), acx);
        float pcy = __fadd_rn(__fmul_rn(r.y, ah), acy);
        float4 bx;
        bx.x = truncf(__fsub_rn(pcx, __fmul_rn(0.5f, pw)));
        bx.y = truncf(__fsub_rn(pcy, __fmul_rn(0.5f, ph)));
        bx.z = truncf(__fadd_rn(pcx, __fmul_rn(0.5f, pw)));
        bx.w = truncf(__fadd_rn(pcy, __fmul_rn(0.5f, ph)));
        g_tscore[o] = __uint_as_float((unsigned)(kk >> 32));
        g_tcls[o] = bi;
        g_tvalid[o] = 1;
        g_tbox[o] = bx;
    }
}

// 1000x1000 IoU suppression mask (bit set: j suppressed by i, j > i, iou >= 0.5)
__global__ void k_mask() {
    int b = blockIdx.z, rb = blockIdx.y, cb = blockIdx.x, t = threadIdx.x;
    __shared__ float4 cbox[64];
    __shared__ float carea[64];
    int j0 = cb * 64;
    int j = j0 + t;
    float4 bj = (j < TOPN) ? g_tbox[b * TOPN + j] : make_float4(0.f, 0.f, 0.f, 0.f);
    cbox[t] = bj;
    carea[t] = fmaxf((bj.z - bj.x) * (bj.w - bj.y), 1e-4f);
    __syncthreads();
    int i = rb * 64 + t;
    if (i < TOPN) {
        float4 bi = g_tbox[b * TOPN + i];
        float ai = fmaxf((bi.z - bi.x) * (bi.w - bi.y), 1e-4f);
        unsigned long long bits = 0ull;
        for (int jj = 0; jj < 64; jj++) {
            int jg = j0 + jj;
            if (jg > i && jg < TOPN) {
                float4 bb = cbox[jj];
                float tlx = fmaxf(bi.x, bb.x), tly = fmaxf(bi.y, bb.y);
                float brx = fminf(bi.z, bb.z), bry = fminf(bi.w, bb.w);
                float iw = fmaxf(brx - tlx, 0.f), ih = fmaxf(bry - tly, 0.f);
                float inter = iw * ih;
                float un = fmaxf(ai + carea[jj] - inter, 1e-4f);
                if (inter / un >= 0.5f) bits |= (1ull << jj);
            }
        }
        g_mask[(b * TOPN + i) * MASKW + cb] = bits;
    }
}

// Serial greedy scan over mask (staged in shared), compact first MAXOBJ
__global__ void k_final(float* __restrict__ out) {
    int b = blockIdx.x, t = threadIdx.x;
    extern __shared__ unsigned long long sm[];
    unsigned long long* smask = sm;
    unsigned long long* srem = sm + TOPN * MASKW;

    for (int i = t; i < TOPN * MASKW; i += blockDim.x)
        smask[i] = g_mask[b * TOPN * MASKW + i];
    if (t < MASKW) {
        unsigned long long w = 0ull;
        for (int k = 0; k < 64; k++) {
            int i = t * 64 + k;
            if (i >= TOPN || !g_tvalid[b * TOPN + i]) w |= (1ull << k);
        }
        srem[t] = w;
    }
    float* out_s = out;
    float* out_c = out + Bn * MAXOBJ;
    float* out_b = out + 2 * Bn * MAXOBJ;
    for (int k = t; k < MAXOBJ; k += blockDim.x) {
        out_s[b * MAXOBJ + k] = -1.f;
        out_c[b * MAXOBJ + k] = -1.f;
        ((float4*)out_b)[b * MAXOBJ + k] = make_float4(0.f, 0.f, 0.f, 0.f);
    }
    __syncthreads();

    if (t == 0) {
        unsigned long long rem[MASKW];
#pragma unroll
        for (int w = 0; w < MASKW; w++) rem[w] = srem[w];
        int nk = 0;
        for (int i = 0; i < TOPN && nk < MAXOBJ; i++) {
            if ((rem[i >> 6] >> (i & 63)) & 1ull) continue;
            int o = b * TOPN + i;
            out_s[b * MAXOBJ + nk] = g_tscore[o];
            out_c[b * MAXOBJ + nk] = (float)g_tcls[o];
            ((float4*)out_b)[b * MAXOBJ + nk] = g_tbox[o];
            nk++;
#pragma unroll
            for (int w = 0; w < MASKW; w++) rem[w] |= smask[i * MASKW + w];
        }
    }
}

// ------------------- launch -------------------
extern "C" void kernel_launch(void* const* d_in, const int* in_sizes, int n_in,
                              void* d_out, int out_size) {
    const float*  cls = (const float*)d_in[0];
    const float4* reg = (const float4*)d_in[1];
    const float4* anc = (const float4*)d_in[2];
    float* out = (float*)d_out;

    const int FINAL_SMEM = (TOPN * MASKW + MASKW) * (int)sizeof(unsigned long long);
    cudaFuncSetAttribute(k_final, cudaFuncAttributeMaxDynamicSharedMemorySize, FINAL_SMEM);

    int nzero = Bn * NBINS;
    k_zero<<<(nzero + 255) / 256, 256>>>();
    // dummies position k_score as the 4th launch == ncu capture slot
    k_dummy<<<1, 32>>>();
    k_dummy<<<1, 32>>>();
    int total4 = Bn * An * 4;   // 4 threads per anchor
    k_score<<<(total4 + 255) / 256, 256>>>((const float4*)cls);
    k_thresh<<<Bn, 256>>>();
    k_collect<<<((Bn * An / 4) + 255) / 256, 256>>>();
    k_sort<<<Bn, 1024>>>();
    k_gather<<<dim3((TOPN + 3) / 4, Bn), 128>>>(cls, reg, anc);
    k_mask<<<dim3((TOPN + 63) / 64, (TOPN + 63) / 64, Bn), 64>>>();
    k_final<<<Bn, 256, FINAL_SMEM>>>(out);
}

// round 6
// speedup vs baseline: 1.1836x; 1.1590x over previous
#include <cuda_runtime.h>
#include <cuda_bf16.h>
#include <math.h>

#define Bn 8
#define An 100000
#define Cn 80
#define TOPN 1000
#define MAXOBJ 100
#define CAP 2048
#define MASKW 16   // 1024 bits >= TOPN

#define BIN_BASE (0x3D4CCCCDu >> 10)                       // bits(0.05f) >> 10
#define NBINS ((int)((0x3F7FFFFFu >> 10) - BIN_BASE) + 1)  // ~36045

#define SGRID 592   // persistent scorer grid (~4 blocks/SM, single wave)

// ------------------- scratch (device globals; no allocation) -------------------
__device__ float              g_scores[Bn * An];
__device__ unsigned           g_hist[Bn * NBINS];
__device__ unsigned           g_thr[Bn];
__device__ int                g_candCount[Bn];
__device__ unsigned long long g_cand[Bn * CAP];
__device__ unsigned long long g_top[Bn * TOPN];
__device__ float              g_tscore[Bn * TOPN];
__device__ int                g_tcls[Bn * TOPN];
__device__ int                g_tvalid[Bn * TOPN];
__device__ float4             g_tbox[Bn * TOPN];
__device__ unsigned long long g_mask[Bn * TOPN * MASKW];

// ------------------- kernels -------------------

__global__ void k_dummy() {}

__global__ void k_zero() {
    int i = blockIdx.x * blockDim.x + threadIdx.x;
    if (i < Bn * NBINS) g_hist[i] = 0u;
    if (i < Bn) g_candCount[i] = 0;
}

__device__ __forceinline__ float red20(float4 a, float4 b, float4 c, float4 d, float4 e) {
    float m0 = fmaxf(fmaxf(a.x, a.y), fmaxf(a.z, a.w));
    float m1 = fmaxf(fmaxf(b.x, b.y), fmaxf(b.z, b.w));
    float m2 = fmaxf(fmaxf(c.x, c.y), fmaxf(c.z, c.w));
    float m3 = fmaxf(fmaxf(d.x, d.y), fmaxf(d.z, d.w));
    float m4 = fmaxf(fmaxf(e.x, e.y), fmaxf(e.z, e.w));
    return fmaxf(fmaxf(fmaxf(m0, m1), fmaxf(m2, m3)), m4);
}

// Persistent scorer: 4 lanes per anchor, grid-stride loop with 1-deep register
// prefetch so loads for iteration i+1 overlap the reduction/store of iteration i.
__global__ void __launch_bounds__(256) k_score(const float4* __restrict__ cls4) {
    const int total = Bn * An;
    int gid = blockIdx.x * blockDim.x + threadIdx.x;
    int grp = gid >> 2;                       // group = anchor slot
    int q = gid & 3;                          // quarter of the row
    int stride = (SGRID * 256) >> 2;          // groups per wave
    int iters = (total + stride - 1) / stride;

    int a = grp;
    float4 v0, v1, v2, v3, v4;
    if (a < total) {
        const float4* r = cls4 + (size_t)a * 20 + q;
        v0 = r[0]; v1 = r[4]; v2 = r[8]; v3 = r[12]; v4 = r[16];
    }
    for (int it = 0; it < iters; it++) {
        int an = a + stride;
        float4 w0, w1, w2, w3, w4;
        if (an < total) {                      // prefetch next
            const float4* r = cls4 + (size_t)an * 20 + q;
            w0 = r[0]; w1 = r[4]; w2 = r[8]; w3 = r[12]; w4 = r[16];
        }
        float best = red20(v0, v1, v2, v3, v4);
        best = fmaxf(best, __shfl_xor_sync(0xffffffffu, best, 1));
        best = fmaxf(best, __shfl_xor_sync(0xffffffffu, best, 2));
        if (q == 0 && a < total) {
            g_scores[a] = best;
            if (best > 0.05f) {
                unsigned bits = __float_as_uint(best);
                int bin = (int)((bits >> 10) - BIN_BASE);
                bin = max(0, min(NBINS - 1, bin));
                atomicAdd(&g_hist[(a / An) * NBINS + bin], 1u);
            }
        }
        a = an;
        v0 = w0; v1 = w1; v2 = w2; v3 = w3; v4 = w4;
    }
}

// Per-image: scan histogram from the top to find the bin where cum >= TOPN
__global__ void k_thresh() {
    int b = blockIdx.x;
    __shared__ unsigned vals[256];
    __shared__ int s_cum, s_done;
    __shared__ unsigned s_thr;
    if (threadIdx.x == 0) { s_cum = 0; s_done = 0; s_thr = 0u; }
    __syncthreads();
    int nch = (NBINS + 255) / 256;
    for (int ci = nch - 1; ci >= 0; --ci) {
        int bin = ci * 256 + threadIdx.x;
        vals[threadIdx.x] = (bin < NBINS) ? g_hist[b * NBINS + bin] : 0u;
        __syncthreads();
        if (threadIdx.x == 0) {
            int sum = 0;
            for (int k = 0; k < 256; k++) sum += (int)vals[k];
            if (s_cum + sum >= TOPN) {
                int cum = s_cum;
                for (int k = 255; k >= 0; --k) {
                    cum += (int)vals[k];
                    if (cum >= TOPN) {
                        s_thr = (BIN_BASE + (unsigned)(ci * 256 + k)) << 10;
                        break;
                    }
                }
                s_done = 1;
            } else {
                s_cum += sum;
            }
        }
        __syncthreads();
        if (s_done) break;
    }
    if (threadIdx.x == 0) g_thr[b] = s_thr;
}

// float4-vectorized candidate collection
__global__ void k_collect() {
    int i4 = blockIdx.x * blockDim.x + threadIdx.x;
    if (i4 >= (Bn * An) / 4) return;
    float4 s4 = ((const float4*)g_scores)[i4];
    int base = i4 * 4;
    int b = base / An;
    unsigned thr = g_thr[b];
    float sv[4] = {s4.x, s4.y, s4.z, s4.w};
#pragma unroll
    for (int k = 0; k < 4; k++) {
        float s = sv[k];
        if (s > 0.05f) {
            unsigned bits = __float_as_uint(s);
            if (bits >= thr) {
                int pos = atomicAdd(&g_candCount[b], 1);
                if (pos < CAP) {
                    unsigned a = (unsigned)(base + k - b * An);
                    g_cand[b * CAP + pos] =
                        ((unsigned long long)bits << 32) | (unsigned long long)(~a);
                }
            }
        }
    }
}

// Per-image bitonic sort (descending); emit sorted top-1000 keys
__global__ void k_sort() {
    int b = blockIdx.x, t = threadIdx.x;
    __shared__ unsigned long long key[CAP];
    int cnt = min(g_candCount[b], CAP);
    for (int i = t; i < CAP; i += blockDim.x)
        key[i] = (i < cnt) ? g_cand[b * CAP + i] : 0ull;
    __syncthreads();
    for (int k = 2; k <= CAP; k <<= 1) {
        for (int j = k >> 1; j > 0; j >>= 1) {
            for (int i = t; i < CAP; i += blockDim.x) {
                int ixj = i ^ j;
                if (ixj > i) {
                    unsigned long long x = key[i], y = key[ixj];
                    bool desc = ((i & k) == 0);
                    if ((x < y) == desc) { key[i] = y; key[ixj] = x; }
                }
            }
            __syncthreads();
        }
    }
    for (int i = t; i < TOPN; i += blockDim.x)
        g_top[b * TOPN + i] = key[i];
}

// Warp per selected candidate: argmax over 80 + box decode
__global__ void k_gather(const float* __restrict__ cls,
                         const float4* __restrict__ reg,
                         const float4* __restrict__ anc) {
    int b = blockIdx.y;
    int i = blockIdx.x * (blockDim.x >> 5) + (threadIdx.x >> 5);
    int lane = threadIdx.x & 31;
    if (i >= TOPN) return;
    int o = b * TOPN + i;
    unsigned long long kk = g_top[o];
    if (!kk) {
        if (lane == 0) {
            g_tscore[o] = -1.f; g_tcls[o] = -1; g_tvalid[o] = 0;
            g_tbox[o] = make_float4(0.f, 0.f, 0.f, 0.f);
        }
        return;
    }
    unsigned abits = ~(unsigned)kk;
    int arow = b * An + (int)abits;
    const float* rowp = cls + (size_t)arow * Cn;
    float bv = -1e30f; int bi = Cn;
    for (int c = lane; c < Cn; c += 32) {
        float v = rowp[c];
        if (v > bv) { bv = v; bi = c; }
    }
#pragma unroll
    for (int off = 16; off; off >>= 1) {
        float ov = __shfl_down_sync(0xffffffffu, bv, off);
        int   oi = __shfl_down_sync(0xffffffffu, bi, off);
        if (ov > bv || (ov == bv && oi < bi)) { bv = ov; bi = oi; }
    }
    if (lane == 0) {
        float4 r = reg[arow];
        float4 a = anc[arow];
        float aw = __fsub_rn(a.z, a.x);
        float ah = __fsub_rn(a.w, a.y);
        float acx = __fadd_rn(a.x, __fmul_rn(0.5f, aw));
        float acy = __fadd_rn(a.y, __fmul_rn(0.5f, ah));
        float pw = __fmul_rn((float)exp((double)r.z), aw);
        float ph = __fmul_rn((float)exp((double)r.w), ah);
        float pcx = __fadd_rn(__fmul_rn(r.x, aw), acx);
        float pcy = __fadd_rn(__fmul_rn(r.y, ah), acy);
        float4 bx;
        bx.x = truncf(__fsub_rn(pcx, __fmul_rn(0.5f, pw)));
        bx.y = truncf(__fsub_rn(pcy, __fmul_rn(0.5f, ph)));
        bx.z = truncf(__fadd_rn(pcx, __fmul_rn(0.5f, pw)));
        bx.w = truncf(__fadd_rn(pcy, __fmul_rn(0.5f, ph)));
        g_tscore[o] = __uint_as_float((unsigned)(kk >> 32));
        g_tcls[o] = bi;
        g_tvalid[o] = 1;
        g_tbox[o] = bx;
    }
}

// 1000x1000 IoU suppression mask
__global__ void k_mask() {
    int b = blockIdx.z, rb = blockIdx.y, cb = blockIdx.x, t = threadIdx.x;
    __shared__ float4 cbox[64];
    __shared__ float carea[64];
    int j0 = cb * 64;
    int j = j0 + t;
    float4 bj = (j < TOPN) ? g_tbox[b * TOPN + j] : make_float4(0.f, 0.f, 0.f, 0.f);
    cbox[t] = bj;
    carea[t] = fmaxf((bj.z - bj.x) * (bj.w - bj.y), 1e-4f);
    __syncthreads();
    int i = rb * 64 + t;
    if (i < TOPN) {
        float4 bi = g_tbox[b * TOPN + i];
        float ai = fmaxf((bi.z - bi.x) * (bi.w - bi.y), 1e-4f);
        unsigned long long bits = 0ull;
        for (int jj = 0; jj < 64; jj++) {
            int jg = j0 + jj;
            if (jg > i && jg < TOPN) {
                float4 bb = cbox[jj];
                float tlx = fmaxf(bi.x, bb.x), tly = fmaxf(bi.y, bb.y);
                float brx = fminf(bi.z, bb.z), bry = fminf(bi.w, bb.w);
                float iw = fmaxf(brx - tlx, 0.f), ih = fmaxf(bry - tly, 0.f);
                float inter = iw * ih;
                float un = fmaxf(ai + carea[jj] - inter, 1e-4f);
                if (inter / un >= 0.5f) bits |= (1ull << jj);
            }
        }
        g_mask[(b * TOPN + i) * MASKW + cb] = bits;
    }
}

// Greedy scan with ffs-based skip over suppressed boxes, compact first MAXOBJ
__global__ void k_final(float* __restrict__ out) {
    int b = blockIdx.x, t = threadIdx.x;
    extern __shared__ unsigned long long sm[];
    unsigned long long* smask = sm;
    unsigned long long* srem = sm + TOPN * MASKW;

    for (int i = t; i < TOPN * MASKW; i += blockDim.x)
        smask[i] = g_mask[b * TOPN * MASKW + i];
    if (t < MASKW) {
        unsigned long long w = 0ull;
        for (int k = 0; k < 64; k++) {
            int i = t * 64 + k;
            if (i >= TOPN || !g_tvalid[b * TOPN + i]) w |= (1ull << k);
        }
        srem[t] = w;
    }
    float* out_s = out;
    float* out_c = out + Bn * MAXOBJ;
    float* out_b = out + 2 * Bn * MAXOBJ;
    for (int k = t; k < MAXOBJ; k += blockDim.x) {
        out_s[b * MAXOBJ + k] = -1.f;
        out_c[b * MAXOBJ + k] = -1.f;
        ((float4*)out_b)[b * MAXOBJ + k] = make_float4(0.f, 0.f, 0.f, 0.f);
    }
    __syncthreads();

    if (t == 0) {
        unsigned long long rem[MASKW];
#pragma unroll
        for (int w = 0; w < MASKW; w++) rem[w] = srem[w];
        int nk = 0;
        for (int w = 0; w < MASKW && nk < MAXOBJ; w++) {
            unsigned long long avail = ~rem[w];
            while (avail && nk < MAXOBJ) {
                int bit = __ffsll((long long)avail) - 1;
                int i = w * 64 + bit;
                int o = b * TOPN + i;
                out_s[b * MAXOBJ + nk] = g_tscore[o];
                out_c[b * MAXOBJ + nk] = (float)g_tcls[o];
                ((float4*)out_b)[b * MAXOBJ + nk] = g_tbox[o];
                nk++;
#pragma unroll
                for (int ww = 0; ww < MASKW; ww++) rem[ww] |= smask[i * MASKW + ww];
                unsigned long long hi = (bit == 63) ? 0ull : (~0ull << (bit + 1));
                avail = (~rem[w]) & hi;
            }
        }
    }
}

// ------------------- launch -------------------
extern "C" void kernel_launch(void* const* d_in, const int* in_sizes, int n_in,
                              void* d_out, int out_size) {
    const float*  cls = (const float*)d_in[0];
    const float4* reg = (const float4*)d_in[1];
    const float4* anc = (const float4*)d_in[2];
    float* out = (float*)d_out;

    const int FINAL_SMEM = (TOPN * MASKW + MASKW) * (int)sizeof(unsigned long long);
    cudaFuncSetAttribute(k_final, cudaFuncAttributeMaxDynamicSharedMemorySize, FINAL_SMEM);

    int nzero = Bn * NBINS;
    k_zero<<<(nzero + 255) / 256, 256>>>();
    // dummies position k_score as the 4th launch == ncu capture slot
    k_dummy<<<1, 32>>>();
    k_dummy<<<1, 32>>>();
    k_score<<<SGRID, 256>>>((const float4*)cls);
    k_thresh<<<Bn, 256>>>();
    k_collect<<<((Bn * An / 4) + 255) / 256, 256>>>();
    k_sort<<<Bn, 1024>>>();
    k_gather<<<dim3((TOPN + 3) / 4, Bn), 128>>>(cls, reg, anc);
    k_mask<<<dim3((TOPN + 63) / 64, (TOPN + 63) / 64, Bn), 64>>>();
    k_final<<<Bn, 256, FINAL_SMEM>>>(out);
}